// round 15
// baseline (speedup 1.0000x reference)
#include <cuda_runtime.h>
#include <cstdint>
#include <math_constants.h>

#define NROWS   131072
#define DDIM    64
#define ECODES  1024
#define BLOCK   256
#define RPB     128
#define GRID_A  (NROWS / RPB)      // 1024
#define NTILES  (ECODES / 8)       // 128 code tiles of 8

__device__ float        g_loss_acc;           // zero-init; reset by last CTA of vq_out
__device__ unsigned int g_ctr;                // zero-init; wraps to 0
__device__ float        g_t2[ECODES];         // exact fp32 ||w_c||^2 (sequential chain)
__device__ float        g_whi[ECODES * DDIM]; // tf32 hi, mma-B-fragment packed
__device__ float        g_wlo[ECODES * DDIM]; // tf32 lo, same layout
__device__ int          g_idx[NROWS];
__device__ int          g_fall[NROWS];
__device__ int          g_nfall;              // reset by prep each call

// ---- prep: exact t2, split-tf32 packed w (hi+lo), reset counter ----
// pack layout (verified in R13): code c = ct*8+g -> slot (ct*32+g*4+q)*16,
//   [kb*2+0] = w[c][kb*8+q], [kb*2+1] = w[c][kb*8+q+4]
__global__ __launch_bounds__(256) void vq_prep(const float* __restrict__ wt) {
    int c = blockIdx.x * blockDim.x + threadIdx.x;
    if (c == 0) g_nfall = 0;
    if (c < ECODES) {
        const float* wr = wt + c * DDIM;
        float v[DDIM];
        float s = 0.0f;
        #pragma unroll
        for (int k = 0; k < DDIM; k++) {
            v[k] = wr[k];
            s = __fadd_rn(s, __fmul_rn(v[k], v[k]));
        }
        g_t2[c] = s;
        int ct = c >> 3, g = c & 7;
        #pragma unroll
        for (int q = 0; q < 4; q++) {
            int base = (ct * 32 + g * 4 + q) * 16;
            #pragma unroll
            for (int kb = 0; kb < 8; kb++) {
                float f0 = v[kb * 8 + q], f1 = v[kb * 8 + q + 4];
                unsigned h0, h1, l0, l1;
                asm("cvt.rna.tf32.f32 %0, %1;" : "=r"(h0) : "f"(f0));
                asm("cvt.rna.tf32.f32 %0, %1;" : "=r"(h1) : "f"(f1));
                float r0 = __fsub_rn(f0, __uint_as_float(h0));
                float r1 = __fsub_rn(f1, __uint_as_float(h1));
                asm("cvt.rna.tf32.f32 %0, %1;" : "=r"(l0) : "f"(r0));
                asm("cvt.rna.tf32.f32 %0, %1;" : "=r"(l1) : "f"(r1));
                g_whi[base + kb * 2]     = __uint_as_float(h0);
                g_whi[base + kb * 2 + 1] = __uint_as_float(h1);
                g_wlo[base + kb * 2]     = __uint_as_float(l0);
                g_wlo[base + kb * 2 + 1] = __uint_as_float(l1);
            }
        }
    }
}

__device__ __forceinline__ void mma_tf32(float& c0, float& c1, float& c2, float& c3,
                                         unsigned a0, unsigned a1, unsigned a2, unsigned a3,
                                         unsigned b0, unsigned b1) {
    asm volatile(
        "mma.sync.aligned.m16n8k8.row.col.f32.tf32.tf32.f32 "
        "{%0,%1,%2,%3}, {%4,%5,%6,%7}, {%8,%9}, {%0,%1,%2,%3};"
        : "+f"(c0), "+f"(c1), "+f"(c2), "+f"(c3)
        : "r"(a0), "r"(a1), "r"(a2), "r"(a3), "r"(b0), "r"(b1));
}

// ---- phase A: split-tf32 prefilter + per-row grid-ulp certificate + enc zero ----
__global__ __launch_bounds__(BLOCK) void vq_filter(
    const float* __restrict__ inp, float* out_enc)
{
    __shared__ float xs[RPB * 66];
    __shared__ float t2s[ECODES];
    __shared__ float t1s[RPB];

    const int tid  = threadIdx.x;
    const int lane = tid & 31;
    const int warp = tid >> 5;        // 8 warps -> 16 rows each
    const int g    = lane >> 2;       // groupID 0..7
    const int q    = lane & 3;        // tig 0..3
    const size_t rowbase = (size_t)blockIdx.x * RPB;

    // stage x + t2
    {
        const float* gx = inp + rowbase * DDIM;
        for (int i = tid; i < RPB * DDIM; i += BLOCK)
            xs[(i >> 6) * 66 + (i & 63)] = gx[i];
        #pragma unroll
        for (int j = 0; j < 4; j++)
            t2s[tid + j * BLOCK] = g_t2[tid + j * BLOCK];
    }
    __syncthreads();

    // exact per-row t1 (sequential k-ascending chain, bit-identical to reference)
    if (tid < RPB) {
        float s = 0.0f;
        #pragma unroll
        for (int k = 0; k < DDIM; k++) {
            float xv = xs[tid * 66 + k];
            s = __fadd_rn(s, __fmul_rn(xv, xv));
        }
        t1s[tid] = s;
    }

    // enc zero (drains during MMA loop; alignment-safe)
    if (out_enc) {
        float* ebase = out_enc + rowbase * (size_t)ECODES;
        const int total = RPB * ECODES;
        const int head = (int)(((16u - ((uintptr_t)ebase & 15u)) & 15u) >> 2);
        if (tid < head) ebase[tid] = 0.0f;
        float4* v = reinterpret_cast<float4*>(ebase + head);
        const int nvec = (total - head) >> 2;
        float4 z = make_float4(0.f, 0.f, 0.f, 0.f);
        for (int i = tid; i < nvec; i += BLOCK) v[i] = z;
        const int tail_start = head + (nvec << 2);
        if (tid < total - tail_start) ebase[tail_start + tid] = 0.0f;
    }
    __syncthreads();

    // A fragments: rows r0 = warp*16+g and r0+8; split hi/lo
    const int r0 = warp * 16 + g;
    unsigned ah[8][4], al[8][4];
    #pragma unroll
    for (int kb = 0; kb < 8; kb++) {
        float f[4] = { xs[r0 * 66 + kb * 8 + q],       xs[(r0 + 8) * 66 + kb * 8 + q],
                       xs[r0 * 66 + kb * 8 + q + 4],   xs[(r0 + 8) * 66 + kb * 8 + q + 4] };
        #pragma unroll
        for (int i = 0; i < 4; i++) {
            unsigned h;
            asm("cvt.rna.tf32.f32 %0, %1;" : "=r"(h) : "f"(f[i]));
            float r = __fsub_rn(f[i], __uint_as_float(h));
            unsigned l;
            asm("cvt.rna.tf32.f32 %0, %1;" : "=r"(l) : "f"(r));
            ah[kb][i] = h; al[kb][i] = l;
        }
    }

    float m1[2] = {CUDART_INF_F, CUDART_INF_F};
    float m2[2] = {CUDART_INF_F, CUDART_INF_F};
    int   i1[2] = {0, 0};
    const float t1a = t1s[r0], t1b = t1s[r0 + 8];

    #pragma unroll 1
    for (int ct = 0; ct < NTILES; ct++) {
        const float4* wh = reinterpret_cast<const float4*>(g_whi) + (ct * 32 + lane) * 4;
        const float4* wl = reinterpret_cast<const float4*>(g_wlo) + (ct * 32 + lane) * 4;
        float4 H[4] = {wh[0], wh[1], wh[2], wh[3]};
        float4 L[4] = {wl[0], wl[1], wl[2], wl[3]};

        float ca0=0.f,ca1=0.f,ca2=0.f,ca3=0.f;   // xl * wh
        float cb0=0.f,cb1=0.f,cb2=0.f,cb3=0.f;   // xh * wl
        float cc0=0.f,cc1=0.f,cc2=0.f,cc3=0.f;   // xh * wh
        #pragma unroll
        for (int kb = 0; kb < 8; kb++) {
            unsigned bh0 = __float_as_uint((kb&1)? ((const float*)&H[kb>>1])[2] : H[kb>>1].x);
            unsigned bh1 = __float_as_uint((kb&1)? ((const float*)&H[kb>>1])[3] : H[kb>>1].y);
            unsigned bl0 = __float_as_uint((kb&1)? ((const float*)&L[kb>>1])[2] : L[kb>>1].x);
            unsigned bl1 = __float_as_uint((kb&1)? ((const float*)&L[kb>>1])[3] : L[kb>>1].y);
            mma_tf32(ca0,ca1,ca2,ca3, al[kb][0],al[kb][1],al[kb][2],al[kb][3], bh0,bh1);
            mma_tf32(cb0,cb1,cb2,cb3, ah[kb][0],ah[kb][1],ah[kb][2],ah[kb][3], bl0,bl1);
            mma_tf32(cc0,cc1,cc2,cc3, ah[kb][0],ah[kb][1],ah[kb][2],ah[kb][3], bh0,bh1);
        }
        float d0 = __fadd_rn(__fadd_rn(ca0, cb0), cc0);
        float d1 = __fadd_rn(__fadd_rn(ca1, cb1), cc1);
        float d2 = __fadd_rn(__fadd_rn(ca2, cb2), cc2);
        float d3 = __fadd_rn(__fadd_rn(ca3, cb3), cc3);

        const int cA = ct * 8 + 2 * q;
        float t2a = t2s[cA], t2b = t2s[cA + 1];
        float dd;
        dd = __fsub_rn(__fadd_rn(t1a, t2a), __fmul_rn(2.0f, d0));
        if (dd < m1[0]) { m2[0] = m1[0]; m1[0] = dd; i1[0] = cA; } else m2[0] = fminf(m2[0], dd);
        dd = __fsub_rn(__fadd_rn(t1a, t2b), __fmul_rn(2.0f, d1));
        if (dd < m1[0]) { m2[0] = m1[0]; m1[0] = dd; i1[0] = cA + 1; } else m2[0] = fminf(m2[0], dd);
        dd = __fsub_rn(__fadd_rn(t1b, t2a), __fmul_rn(2.0f, d2));
        if (dd < m1[1]) { m2[1] = m1[1]; m1[1] = dd; i1[1] = cA; } else m2[1] = fminf(m2[1], dd);
        dd = __fsub_rn(__fadd_rn(t1b, t2b), __fmul_rn(2.0f, d3));
        if (dd < m1[1]) { m2[1] = m1[1]; m1[1] = dd; i1[1] = cA + 1; } else m2[1] = fminf(m2[1], dd);
    }

    // merge across the 4 q-lanes (xor 1,2) with first-index tie-break
    #pragma unroll
    for (int r = 0; r < 2; r++) {
        float a1 = m1[r]; int ai = i1[r]; float a2 = m2[r];
        #pragma unroll
        for (int off = 1; off <= 2; off <<= 1) {
            float o1 = __shfl_xor_sync(0xffffffffu, a1, off);
            int   oi = __shfl_xor_sync(0xffffffffu, ai, off);
            float o2 = __shfl_xor_sync(0xffffffffu, a2, off);
            float hi = fmaxf(a1, o1);            // on tie: hi==a1 -> m2<=m1 -> fallback
            if (o1 < a1 || (o1 == a1 && oi < ai)) { a1 = o1; ai = oi; }
            a2 = fminf(fminf(a2, o2), hi);
        }
        if (q == 0) {
            int grow = (int)rowbase + warp * 16 + g + r * 8;
            g_idx[grow] = ai;
            // certificate: gap must exceed 4*ulp(result) + 4e-6 (covers <=1-ulp grid
            // shift of every approx value vs the reference's grid value)
            unsigned b = __float_as_uint(fmaxf(fabsf(a1), 1.0f));
            int e = (int)((b >> 23) & 0xffu);
            float ulp = __uint_as_float((unsigned)(e - 23) << 23);
            float thr = __fmaf_rn(4.0f, ulp, 4e-6f);
            if (!(a2 - a1 > thr)) {
                int p = atomicAdd(&g_nfall, 1);
                g_fall[p] = grow;
            }
        }
    }
}

// ---- phase B: exact rescan, smem-chunked, bit-exact reference arithmetic ----
__global__ __launch_bounds__(256) void vq_exact(
    const float* __restrict__ inp, const float* __restrict__ wt)
{
    __shared__ float wch[128 * 66];
    const int tid = threadIdx.x;
    const int lane = tid & 31;
    const int warp = tid >> 5;
    const int n = *((volatile int*)&g_nfall);
    const int per_pass = gridDim.x * 8;
    const int nbatch = (n + per_pass - 1) / per_pass;

    for (int b = 0; b < nbatch; b++) {
        int ri = (b * gridDim.x + blockIdx.x) * 8 + warp;
        bool valid = ri < n;
        int row = valid ? g_fall[ri] : 0;

        float x[DDIM];
        {
            const float4* xr = reinterpret_cast<const float4*>(inp + (size_t)row * DDIM);
            #pragma unroll
            for (int k4 = 0; k4 < 16; k4++) {
                float4 v = xr[k4];
                x[4*k4]=v.x; x[4*k4+1]=v.y; x[4*k4+2]=v.z; x[4*k4+3]=v.w;
            }
        }
        float t1 = 0.0f;
        #pragma unroll
        for (int k = 0; k < DDIM; k++)
            t1 = __fadd_rn(t1, __fmul_rn(x[k], x[k]));

        float best = CUDART_INF_F; int bi = 0;
        for (int ch = 0; ch < 8; ch++) {
            __syncthreads();
            for (int i = tid; i < 128 * DDIM; i += 256)
                wch[(i >> 6) * 66 + (i & 63)] = wt[ch * 128 * DDIM + i];
            __syncthreads();
            if (valid) {
                #pragma unroll
                for (int j = 0; j < 4; j++) {
                    int cl = lane + 32 * j;            // ascending per lane
                    const float* wr = wch + cl * 66;
                    float dacc = 0.0f;
                    #pragma unroll
                    for (int k = 0; k < DDIM; k++)
                        dacc = __fmaf_rn(x[k], wr[k], dacc);
                    int c = ch * 128 + cl;
                    float u = __fadd_rn(t1, g_t2[c]);
                    float dist = __fsub_rn(u, __fmul_rn(2.0f, dacc));
                    if (dist < best) { best = dist; bi = c; }
                }
            }
        }
        #pragma unroll
        for (int off = 1; off < 32; off <<= 1) {
            float ob = __shfl_xor_sync(0xffffffffu, best, off);
            int   oi = __shfl_xor_sync(0xffffffffu, bi, off);
            if (ob < best || (ob == best && oi < bi)) { best = ob; bi = oi; }
        }
        if (valid && lane == 0) g_idx[row] = bi;
    }
}

// ---- phase C: scatter ones + quantized + loss (R13-verified) ----
__global__ __launch_bounds__(BLOCK) void vq_out(
    const float* __restrict__ inp, const float* __restrict__ wt,
    float* out_q, float* out_enc, float* out_loss)
{
    __shared__ int   idx_sh[RPB];
    __shared__ float red[BLOCK];
    const int tid = threadIdx.x;
    const size_t rowbase = (size_t)blockIdx.x * RPB;

    if (tid < RPB) idx_sh[tid] = g_idx[rowbase + tid];
    __syncthreads();

    if (out_enc && tid < RPB)
        out_enc[(rowbase + tid) * (size_t)ECODES + (size_t)idx_sh[tid]] = 1.0f;

    float part = 0.0f;
    for (int i = tid; i < RPB * DDIM; i += BLOCK) {
        int r = i >> 6, k = i & 63;
        float qv = wt[(size_t)idx_sh[r] * DDIM + k];
        float xv = inp[(rowbase + r) * DDIM + k];
        float dqx = __fsub_rn(qv, xv);
        part = __fadd_rn(part, __fmul_rn(dqx, dqx));
        if (out_q)
            out_q[rowbase * DDIM + i] = __fadd_rn(xv, dqx);
    }
    red[tid] = part;
    __syncthreads();
    for (int s = BLOCK / 2; s > 0; s >>= 1) {
        if (tid < s) red[tid] += red[tid + s];
        __syncthreads();
    }
    if (tid == 0) {
        atomicAdd(&g_loss_acc, red[0]);
        __threadfence();
        unsigned int done = atomicAdd(&g_ctr, 1u);
        if (done == GRID_A - 1) {
            float m = *((volatile float*)&g_loss_acc) / 8388608.0f;
            if (out_loss) out_loss[0] = __fadd_rn(m, __fmul_rn(0.25f, m));
            g_loss_acc = 0.0f;
            __threadfence();
            g_ctr = 0u;
        }
    }
}

extern "C" void kernel_launch(void* const* d_in, const int* in_sizes, int n_in,
                              void* d_out, int out_size)
{
    const float* inp = nullptr;
    const float* wt  = nullptr;
    for (int i = 0; i < n_in; i++) {
        if (in_sizes[i] == 8388608) inp = (const float*)d_in[i];
        else if (in_sizes[i] == 65536) wt = (const float*)d_in[i];
    }
    if (!inp || !wt) return;

    float* out = (float*)d_out;
    const long long Q = 8388608LL, ENC = 134217728LL;
    long long os = (long long)out_size;

    float* oL = nullptr; float* oQ = nullptr; float* oE = nullptr;
    if (os == 1 + Q + ENC)      { oL = out; oQ = out + 1; oE = out + 1 + Q; }
    else if (os == Q + ENC)     { oQ = out; oE = out + Q; }
    else if (os == ENC)         { oE = out; }
    else if (os == Q)           { oQ = out; }
    else if (os == 1)           { oL = out; }
    else {
        oL = out;
        if (os >= 1 + Q) oQ = out + 1;
        if (os >= 1 + Q + ENC) oE = out + 1 + Q;
    }

    vq_prep<<<4, 256>>>(wt);
    vq_filter<<<GRID_A, BLOCK>>>(inp, oE);
    vq_exact<<<148, 256>>>(inp, wt);
    vq_out<<<GRID_A, BLOCK>>>(inp, wt, oQ, oE, oL);
}

// round 16
// speedup vs baseline: 1.7290x; 1.7290x over previous
#include <cuda_runtime.h>
#include <cstdint>
#include <math_constants.h>

#define NROWS   131072
#define DDIM    64
#define ECODES  1024
#define BLOCK   256
#define RPB     128
#define GRID_A  (NROWS / RPB)      // 1024
#define NTILES  (ECODES / 8)       // 128 code tiles of 8
#define TPC     16                 // tiles per smem chunk (128 codes)
#define NCHUNKS (NTILES / TPC)     // 8

// filter smem offsets (bytes)
#define OFF_XS  0                       // 128*66 floats = 33792
#define OFF_WH  33792                   // 4096 float2 = 32768
#define OFF_WL  66560                   // 4096 float2 = 32768
#define OFF_T2F 99328                   // 1024 floats = 4096
#define OFF_T1F 103424                  // 128 floats = 512
#define SMEMF   103936

__device__ float        g_loss_acc;
__device__ unsigned int g_ctr;
__device__ float        g_t2[ECODES];
__device__ float2       g_whi2[NTILES * 8 * 32];   // [ct][kb][lane] tf32-hi b-frags
__device__ float2       g_wlo2[NTILES * 8 * 32];   // same, tf32-lo
__device__ int          g_idx[NROWS];
__device__ int          g_fall[NROWS];
__device__ int          g_nfall;

// ---- prep: exact t2; split-tf32 w packed [ct][kb][lane]; reset counter ----
__global__ __launch_bounds__(256) void vq_prep(const float* __restrict__ wt) {
    int c = blockIdx.x * blockDim.x + threadIdx.x;
    if (c == 0) g_nfall = 0;
    if (c < ECODES) {
        const float* wr = wt + c * DDIM;
        float v[DDIM];
        float s = 0.0f;
        #pragma unroll
        for (int k = 0; k < DDIM; k++) {
            v[k] = wr[k];
            s = __fadd_rn(s, __fmul_rn(v[k], v[k]));
        }
        g_t2[c] = s;
        int ct = c >> 3, g = c & 7;
        #pragma unroll
        for (int q = 0; q < 4; q++) {
            int lane = g * 4 + q;
            #pragma unroll
            for (int kb = 0; kb < 8; kb++) {
                float f0 = v[kb * 8 + q], f1 = v[kb * 8 + q + 4];
                unsigned h0, h1, l0, l1;
                asm("cvt.rna.tf32.f32 %0, %1;" : "=r"(h0) : "f"(f0));
                asm("cvt.rna.tf32.f32 %0, %1;" : "=r"(h1) : "f"(f1));
                float r0 = __fsub_rn(f0, __uint_as_float(h0));
                float r1 = __fsub_rn(f1, __uint_as_float(h1));
                asm("cvt.rna.tf32.f32 %0, %1;" : "=r"(l0) : "f"(r0));
                asm("cvt.rna.tf32.f32 %0, %1;" : "=r"(l1) : "f"(r1));
                int s2 = (ct * 8 + kb) * 32 + lane;
                g_whi2[s2] = make_float2(__uint_as_float(h0), __uint_as_float(h1));
                g_wlo2[s2] = make_float2(__uint_as_float(l0), __uint_as_float(l1));
            }
        }
    }
}

__device__ __forceinline__ void mma_tf32(float& c0, float& c1, float& c2, float& c3,
                                         unsigned a0, unsigned a1, unsigned a2, unsigned a3,
                                         unsigned b0, unsigned b1) {
    asm volatile(
        "mma.sync.aligned.m16n8k8.row.col.f32.tf32.tf32.f32 "
        "{%0,%1,%2,%3}, {%4,%5,%6,%7}, {%8,%9}, {%0,%1,%2,%3};"
        : "+f"(c0), "+f"(c1), "+f"(c2), "+f"(c3)
        : "r"(a0), "r"(a1), "r"(a2), "r"(a3), "r"(b0), "r"(b1));
}

// ---- phase A: split-tf32 prefilter (smem-staged w) + certificate + enc zero ----
__global__ __launch_bounds__(BLOCK, 2) void vq_filter(
    const float* __restrict__ inp, float* out_enc)
{
    extern __shared__ __align__(16) char sm[];
    float*  xs   = reinterpret_cast<float*>(sm + OFF_XS);    // [128][66]
    float2* whsm = reinterpret_cast<float2*>(sm + OFF_WH);   // [16 tiles][8][32]
    float2* wlsm = reinterpret_cast<float2*>(sm + OFF_WL);
    float*  t2s  = reinterpret_cast<float*>(sm + OFF_T2F);   // [1024]
    float*  t1s  = reinterpret_cast<float*>(sm + OFF_T1F);   // [128]

    const int tid  = threadIdx.x;
    const int lane = tid & 31;
    const int warp = tid >> 5;        // 8 warps, 16 rows each
    const int g    = lane >> 2;
    const int q    = lane & 3;
    const size_t rowbase = (size_t)blockIdx.x * RPB;

    // stage x + t2
    {
        const float* gx = inp + rowbase * DDIM;
        for (int i = tid; i < RPB * DDIM; i += BLOCK)
            xs[(i >> 6) * 66 + (i & 63)] = gx[i];
        #pragma unroll
        for (int j = 0; j < 4; j++)
            t2s[tid + j * BLOCK] = g_t2[tid + j * BLOCK];
    }
    __syncthreads();

    // exact per-row t1 (sequential k-ascending, reference-identical)
    if (tid < RPB) {
        float s = 0.0f;
        #pragma unroll
        for (int k = 0; k < DDIM; k++) {
            float xv = xs[tid * 66 + k];
            s = __fadd_rn(s, __fmul_rn(xv, xv));
        }
        t1s[tid] = s;
    }

    // enc zero (drains during compute; alignment-safe)
    if (out_enc) {
        float* ebase = out_enc + rowbase * (size_t)ECODES;
        const int total = RPB * ECODES;
        const int head = (int)(((16u - ((uintptr_t)ebase & 15u)) & 15u) >> 2);
        if (tid < head) ebase[tid] = 0.0f;
        float4* v = reinterpret_cast<float4*>(ebase + head);
        const int nvec = (total - head) >> 2;
        float4 z = make_float4(0.f, 0.f, 0.f, 0.f);
        for (int i = tid; i < nvec; i += BLOCK) v[i] = z;
        const int tail_start = head + (nvec << 2);
        if (tid < total - tail_start) ebase[tail_start + tid] = 0.0f;
    }
    __syncthreads();

    // A fragments (rows r0, r0+8), split hi/lo; 64 regs persistent
    const int r0 = warp * 16 + g;
    unsigned ah[8][4], al[8][4];
    #pragma unroll
    for (int kb = 0; kb < 8; kb++) {
        float f[4] = { xs[r0 * 66 + kb * 8 + q],       xs[(r0 + 8) * 66 + kb * 8 + q],
                       xs[r0 * 66 + kb * 8 + q + 4],   xs[(r0 + 8) * 66 + kb * 8 + q + 4] };
        #pragma unroll
        for (int i = 0; i < 4; i++) {
            unsigned h;
            asm("cvt.rna.tf32.f32 %0, %1;" : "=r"(h) : "f"(f[i]));
            float r = __fsub_rn(f[i], __uint_as_float(h));
            unsigned l;
            asm("cvt.rna.tf32.f32 %0, %1;" : "=r"(l) : "f"(r));
            ah[kb][i] = h; al[kb][i] = l;
        }
    }

    float m1[2] = {CUDART_INF_F, CUDART_INF_F};
    float m2[2] = {CUDART_INF_F, CUDART_INF_F};
    int   i1[2] = {0, 0};
    const float t1a = t1s[r0], t1b = t1s[r0 + 8];

    for (int chunk = 0; chunk < NCHUNKS; chunk++) {
        __syncthreads();
        // stage 16 tiles (128 codes) of hi+lo b-fragments: contiguous 32KB each
        {
            const float4* sh = reinterpret_cast<const float4*>(g_whi2 + chunk * (TPC * 8 * 32));
            const float4* sl = reinterpret_cast<const float4*>(g_wlo2 + chunk * (TPC * 8 * 32));
            float4* dh = reinterpret_cast<float4*>(whsm);
            float4* dl = reinterpret_cast<float4*>(wlsm);
            #pragma unroll 4
            for (int i = tid; i < 2048; i += BLOCK) { dh[i] = sh[i]; dl[i] = sl[i]; }
        }
        __syncthreads();

        #pragma unroll 1
        for (int tl = 0; tl < TPC; tl++) {
            const int ct = chunk * TPC + tl;
            float ca0=0.f,ca1=0.f,ca2=0.f,ca3=0.f;   // xl * wh
            float cb0=0.f,cb1=0.f,cb2=0.f,cb3=0.f;   // xh * wl
            float cc0=0.f,cc1=0.f,cc2=0.f,cc3=0.f;   // xh * wh
            #pragma unroll
            for (int kb = 0; kb < 8; kb++) {
                float2 bh = whsm[(tl * 8 + kb) * 32 + lane];
                float2 bl = wlsm[(tl * 8 + kb) * 32 + lane];
                unsigned bh0 = __float_as_uint(bh.x), bh1 = __float_as_uint(bh.y);
                unsigned bl0 = __float_as_uint(bl.x), bl1 = __float_as_uint(bl.y);
                mma_tf32(ca0,ca1,ca2,ca3, al[kb][0],al[kb][1],al[kb][2],al[kb][3], bh0,bh1);
                mma_tf32(cb0,cb1,cb2,cb3, ah[kb][0],ah[kb][1],ah[kb][2],ah[kb][3], bl0,bl1);
                mma_tf32(cc0,cc1,cc2,cc3, ah[kb][0],ah[kb][1],ah[kb][2],ah[kb][3], bh0,bh1);
            }
            float d0 = __fadd_rn(__fadd_rn(ca0, cb0), cc0);
            float d1 = __fadd_rn(__fadd_rn(ca1, cb1), cc1);
            float d2 = __fadd_rn(__fadd_rn(ca2, cb2), cc2);
            float d3 = __fadd_rn(__fadd_rn(ca3, cb3), cc3);

            const int cA = ct * 8 + 2 * q;
            float t2a = t2s[cA], t2b = t2s[cA + 1];
            float dd;
            dd = __fsub_rn(__fadd_rn(t1a, t2a), __fmul_rn(2.0f, d0));
            if (dd < m1[0]) { m2[0] = m1[0]; m1[0] = dd; i1[0] = cA; } else m2[0] = fminf(m2[0], dd);
            dd = __fsub_rn(__fadd_rn(t1a, t2b), __fmul_rn(2.0f, d1));
            if (dd < m1[0]) { m2[0] = m1[0]; m1[0] = dd; i1[0] = cA + 1; } else m2[0] = fminf(m2[0], dd);
            dd = __fsub_rn(__fadd_rn(t1b, t2a), __fmul_rn(2.0f, d2));
            if (dd < m1[1]) { m2[1] = m1[1]; m1[1] = dd; i1[1] = cA; } else m2[1] = fminf(m2[1], dd);
            dd = __fsub_rn(__fadd_rn(t1b, t2b), __fmul_rn(2.0f, d3));
            if (dd < m1[1]) { m2[1] = m1[1]; m1[1] = dd; i1[1] = cA + 1; } else m2[1] = fminf(m2[1], dd);
        }
    }

    // merge across the 4 q-lanes (xor 1,2), first-index ties; ties force fallback
    #pragma unroll
    for (int r = 0; r < 2; r++) {
        float a1 = m1[r]; int ai = i1[r]; float a2 = m2[r];
        #pragma unroll
        for (int off = 1; off <= 2; off <<= 1) {
            float o1 = __shfl_xor_sync(0xffffffffu, a1, off);
            int   oi = __shfl_xor_sync(0xffffffffu, ai, off);
            float o2 = __shfl_xor_sync(0xffffffffu, a2, off);
            float hi = fmaxf(a1, o1);
            if (o1 < a1 || (o1 == a1 && oi < ai)) { a1 = o1; ai = oi; }
            a2 = fminf(fminf(a2, o2), hi);
        }
        if (q == 0) {
            int grow = (int)rowbase + warp * 16 + g + r * 8;
            g_idx[grow] = ai;
            unsigned b = __float_as_uint(fmaxf(fabsf(a1), 1.0f));
            int e = (int)((b >> 23) & 0xffu);
            float ulp = __uint_as_float((unsigned)(e - 23) << 23);
            float thr = __fmaf_rn(4.0f, ulp, 4e-6f);
            if (!(a2 - a1 > thr)) {
                int p = atomicAdd(&g_nfall, 1);
                g_fall[p] = grow;
            }
        }
    }
}

// ---- phase B: exact rescan, smem-chunked, bit-exact reference arithmetic ----
__global__ __launch_bounds__(256) void vq_exact(
    const float* __restrict__ inp, const float* __restrict__ wt)
{
    __shared__ float wch[128 * 66];
    const int tid = threadIdx.x;
    const int lane = tid & 31;
    const int warp = tid >> 5;
    const int n = *((volatile int*)&g_nfall);
    const int per_pass = gridDim.x * 8;
    const int nbatch = (n + per_pass - 1) / per_pass;

    for (int b = 0; b < nbatch; b++) {
        int ri = (b * gridDim.x + blockIdx.x) * 8 + warp;
        bool valid = ri < n;
        int row = valid ? g_fall[ri] : 0;

        float x[DDIM];
        {
            const float4* xr = reinterpret_cast<const float4*>(inp + (size_t)row * DDIM);
            #pragma unroll
            for (int k4 = 0; k4 < 16; k4++) {
                float4 v = xr[k4];
                x[4*k4]=v.x; x[4*k4+1]=v.y; x[4*k4+2]=v.z; x[4*k4+3]=v.w;
            }
        }
        float t1 = 0.0f;
        #pragma unroll
        for (int k = 0; k < DDIM; k++)
            t1 = __fadd_rn(t1, __fmul_rn(x[k], x[k]));

        float best = CUDART_INF_F; int bi = 0;
        for (int ch = 0; ch < 8; ch++) {
            __syncthreads();
            for (int i = tid; i < 128 * DDIM; i += 256)
                wch[(i >> 6) * 66 + (i & 63)] = wt[ch * 128 * DDIM + i];
            __syncthreads();
            if (valid) {
                #pragma unroll
                for (int j = 0; j < 4; j++) {
                    int cl = lane + 32 * j;
                    const float* wr = wch + cl * 66;
                    float dacc = 0.0f;
                    #pragma unroll
                    for (int k = 0; k < DDIM; k++)
                        dacc = __fmaf_rn(x[k], wr[k], dacc);
                    int c = ch * 128 + cl;
                    float u = __fadd_rn(t1, g_t2[c]);
                    float dist = __fsub_rn(u, __fmul_rn(2.0f, dacc));
                    if (dist < best) { best = dist; bi = c; }
                }
            }
        }
        #pragma unroll
        for (int off = 1; off < 32; off <<= 1) {
            float ob = __shfl_xor_sync(0xffffffffu, best, off);
            int   oi = __shfl_xor_sync(0xffffffffu, bi, off);
            if (ob < best || (ob == best && oi < bi)) { best = ob; bi = oi; }
        }
        if (valid && lane == 0) g_idx[row] = bi;
    }
}

// ---- phase C: scatter ones + quantized + loss ----
__global__ __launch_bounds__(BLOCK) void vq_out(
    const float* __restrict__ inp, const float* __restrict__ wt,
    float* out_q, float* out_enc, float* out_loss)
{
    __shared__ int   idx_sh[RPB];
    __shared__ float red[BLOCK];
    const int tid = threadIdx.x;
    const size_t rowbase = (size_t)blockIdx.x * RPB;

    if (tid < RPB) idx_sh[tid] = g_idx[rowbase + tid];
    __syncthreads();

    if (out_enc && tid < RPB)
        out_enc[(rowbase + tid) * (size_t)ECODES + (size_t)idx_sh[tid]] = 1.0f;

    float part = 0.0f;
    for (int i = tid; i < RPB * DDIM; i += BLOCK) {
        int r = i >> 6, k = i & 63;
        float qv = wt[(size_t)idx_sh[r] * DDIM + k];
        float xv = inp[(rowbase + r) * DDIM + k];
        float dqx = __fsub_rn(qv, xv);
        part = __fadd_rn(part, __fmul_rn(dqx, dqx));
        if (out_q)
            out_q[rowbase * DDIM + i] = __fadd_rn(xv, dqx);
    }
    red[tid] = part;
    __syncthreads();
    for (int s = BLOCK / 2; s > 0; s >>= 1) {
        if (tid < s) red[tid] += red[tid + s];
        __syncthreads();
    }
    if (tid == 0) {
        atomicAdd(&g_loss_acc, red[0]);
        __threadfence();
        unsigned int done = atomicAdd(&g_ctr, 1u);
        if (done == GRID_A - 1) {
            float m = *((volatile float*)&g_loss_acc) / 8388608.0f;
            if (out_loss) out_loss[0] = __fadd_rn(m, __fmul_rn(0.25f, m));
            g_loss_acc = 0.0f;
            __threadfence();
            g_ctr = 0u;
        }
    }
}

extern "C" void kernel_launch(void* const* d_in, const int* in_sizes, int n_in,
                              void* d_out, int out_size)
{
    const float* inp = nullptr;
    const float* wt  = nullptr;
    for (int i = 0; i < n_in; i++) {
        if (in_sizes[i] == 8388608) inp = (const float*)d_in[i];
        else if (in_sizes[i] == 65536) wt = (const float*)d_in[i];
    }
    if (!inp || !wt) return;

    float* out = (float*)d_out;
    const long long Q = 8388608LL, ENC = 134217728LL;
    long long os = (long long)out_size;

    float* oL = nullptr; float* oQ = nullptr; float* oE = nullptr;
    if (os == 1 + Q + ENC)      { oL = out; oQ = out + 1; oE = out + 1 + Q; }
    else if (os == Q + ENC)     { oQ = out; oE = out + Q; }
    else if (os == ENC)         { oE = out; }
    else if (os == Q)           { oQ = out; }
    else if (os == 1)           { oL = out; }
    else {
        oL = out;
        if (os >= 1 + Q) oQ = out + 1;
        if (os >= 1 + Q + ENC) oE = out + 1 + Q;
    }

    cudaFuncSetAttribute(vq_filter,
                         cudaFuncAttributeMaxDynamicSharedMemorySize, SMEMF);

    vq_prep<<<4, 256>>>(wt);
    vq_filter<<<GRID_A, BLOCK, SMEMF>>>(inp, oE);
    vq_exact<<<148, 256>>>(inp, wt);
    vq_out<<<GRID_A, BLOCK>>>(inp, wt, oQ, oE, oL);
}

// round 17
// speedup vs baseline: 2.3296x; 1.3473x over previous
#include <cuda_runtime.h>
#include <cuda_bf16.h>
#include <cstdint>
#include <math_constants.h>

#define NROWS   131072
#define DDIM    64
#define ECODES  1024
#define BLOCK   256
#define RPB     128
#define GRID_A  (NROWS / RPB)      // 1024
#define NTILES  (ECODES / 8)       // 128 code tiles of 8
#define TPC     16                 // tiles per smem chunk (128 codes)
#define NCHUNKS (NTILES / TPC)     // 8

// filter smem offsets (bytes)
#define OFF_XS   0                      // 128*66 floats = 33792
#define OFF_WPK  33792                  // 16*4*32 uint4 = 32768
#define OFF_T2F  66560                  // 1024 floats = 4096
#define OFF_T1F  70656                  // 128 floats = 512
#define SMEMF    71168

__device__ float        g_loss_acc;
__device__ unsigned int g_ctr;
__device__ float        g_t2[ECODES];
__device__ uint4        g_wpk[NTILES * 4 * 32];   // [ct][kb2][lane] {bh0,bh1,bl0,bl1}
__device__ int          g_idx[NROWS];
__device__ int          g_fall[NROWS];
__device__ int          g_nfall;

__device__ __forceinline__ unsigned pack_bf16(float lo, float hi) {
    unsigned r;
    asm("cvt.rn.bf16x2.f32 %0, %1, %2;" : "=r"(r) : "f"(hi), "f"(lo));
    return r;
}
__device__ __forceinline__ void split_bf16(float f, float& h, float& l) {
    __nv_bfloat16 hb = __float2bfloat16_rn(f);
    h = __bfloat162float(hb);
    l = __fsub_rn(f, h);           // exact lo-part source; packed as bf16 later
}

// ---- prep: exact t2; split-bf16 w packed as m16n8k16 B-fragments; reset counter ----
__global__ __launch_bounds__(256) void vq_prep(const float* __restrict__ wt) {
    int c = blockIdx.x * blockDim.x + threadIdx.x;
    if (c == 0) g_nfall = 0;
    if (c < ECODES) {
        const float* wr = wt + c * DDIM;
        float v[DDIM], vh[DDIM], vl[DDIM];
        float s = 0.0f;
        #pragma unroll
        for (int k = 0; k < DDIM; k++) {
            v[k] = wr[k];
            s = __fadd_rn(s, __fmul_rn(v[k], v[k]));
            split_bf16(v[k], vh[k], vl[k]);
        }
        g_t2[c] = s;
        int ct = c >> 3, g = c & 7;
        #pragma unroll
        for (int kb2 = 0; kb2 < 4; kb2++) {
            #pragma unroll
            for (int q = 0; q < 4; q++) {
                int k0 = kb2 * 16 + 2 * q;
                uint4 u;
                u.x = pack_bf16(vh[k0],     vh[k0 + 1]);   // bh0: k={2q,2q+1}
                u.y = pack_bf16(vh[k0 + 8], vh[k0 + 9]);   // bh1: k={2q+8,2q+9}
                u.z = pack_bf16(vl[k0],     vl[k0 + 1]);   // bl0
                u.w = pack_bf16(vl[k0 + 8], vl[k0 + 9]);   // bl1
                g_wpk[(ct * 4 + kb2) * 32 + g * 4 + q] = u;
            }
        }
    }
}

__device__ __forceinline__ void mma_bf16(float& c0, float& c1, float& c2, float& c3,
                                         unsigned a0, unsigned a1, unsigned a2, unsigned a3,
                                         unsigned b0, unsigned b1) {
    asm volatile(
        "mma.sync.aligned.m16n8k16.row.col.f32.bf16.bf16.f32 "
        "{%0,%1,%2,%3}, {%4,%5,%6,%7}, {%8,%9}, {%0,%1,%2,%3};"
        : "+f"(c0), "+f"(c1), "+f"(c2), "+f"(c3)
        : "r"(a0), "r"(a1), "r"(a2), "r"(a3), "r"(b0), "r"(b1));
}

// ---- phase A: split-bf16 prefilter + grid-ulp certificate + enc zero ----
__global__ __launch_bounds__(BLOCK, 2) void vq_filter(
    const float* __restrict__ inp, float* out_enc)
{
    extern __shared__ __align__(16) char sm[];
    float* xs   = reinterpret_cast<float*>(sm + OFF_XS);    // [128][66]
    uint4* wpk  = reinterpret_cast<uint4*>(sm + OFF_WPK);   // [16][4][32]
    float* t2s  = reinterpret_cast<float*>(sm + OFF_T2F);   // [1024]
    float* t1s  = reinterpret_cast<float*>(sm + OFF_T1F);   // [128]

    const int tid  = threadIdx.x;
    const int lane = tid & 31;
    const int warp = tid >> 5;        // 8 warps, 16 rows each
    const int g    = lane >> 2;
    const int q    = lane & 3;
    const size_t rowbase = (size_t)blockIdx.x * RPB;

    // stage x + t2
    {
        const float* gx = inp + rowbase * DDIM;
        for (int i = tid; i < RPB * DDIM; i += BLOCK)
            xs[(i >> 6) * 66 + (i & 63)] = gx[i];
        #pragma unroll
        for (int j = 0; j < 4; j++)
            t2s[tid + j * BLOCK] = g_t2[tid + j * BLOCK];
    }
    __syncthreads();

    // exact per-row t1 (sequential k-ascending, reference-identical)
    if (tid < RPB) {
        float s = 0.0f;
        #pragma unroll
        for (int k = 0; k < DDIM; k++) {
            float xv = xs[tid * 66 + k];
            s = __fadd_rn(s, __fmul_rn(xv, xv));
        }
        t1s[tid] = s;
    }

    // enc zero (drains during compute; alignment-safe)
    if (out_enc) {
        float* ebase = out_enc + rowbase * (size_t)ECODES;
        const int total = RPB * ECODES;
        const int head = (int)(((16u - ((uintptr_t)ebase & 15u)) & 15u) >> 2);
        if (tid < head) ebase[tid] = 0.0f;
        float4* v = reinterpret_cast<float4*>(ebase + head);
        const int nvec = (total - head) >> 2;
        float4 z = make_float4(0.f, 0.f, 0.f, 0.f);
        for (int i = tid; i < nvec; i += BLOCK) v[i] = z;
        const int tail_start = head + (nvec << 2);
        if (tid < total - tail_start) ebase[tail_start + tid] = 0.0f;
    }
    __syncthreads();

    // A fragments (rows r0, r0+8), bf16 hi/lo: ah/al[kb2][4] = 32 regs
    const int r0 = warp * 16 + g;
    unsigned ah[4][4], al[4][4];
    #pragma unroll
    for (int kb2 = 0; kb2 < 4; kb2++) {
        int k0 = kb2 * 16 + 2 * q;
        float fh[8], fl[8];
        // order: a0 = (r0, k0..k0+1), a1 = (r0+8, k0..), a2 = (r0, k0+8..), a3 = (r0+8, k0+8..)
        split_bf16(xs[r0 * 66 + k0],           fh[0], fl[0]);
        split_bf16(xs[r0 * 66 + k0 + 1],       fh[1], fl[1]);
        split_bf16(xs[(r0 + 8) * 66 + k0],     fh[2], fl[2]);
        split_bf16(xs[(r0 + 8) * 66 + k0 + 1], fh[3], fl[3]);
        split_bf16(xs[r0 * 66 + k0 + 8],       fh[4], fl[4]);
        split_bf16(xs[r0 * 66 + k0 + 9],       fh[5], fl[5]);
        split_bf16(xs[(r0 + 8) * 66 + k0 + 8], fh[6], fl[6]);
        split_bf16(xs[(r0 + 8) * 66 + k0 + 9], fh[7], fl[7]);
        ah[kb2][0] = pack_bf16(fh[0], fh[1]);  al[kb2][0] = pack_bf16(fl[0], fl[1]);
        ah[kb2][1] = pack_bf16(fh[2], fh[3]);  al[kb2][1] = pack_bf16(fl[2], fl[3]);
        ah[kb2][2] = pack_bf16(fh[4], fh[5]);  al[kb2][2] = pack_bf16(fl[4], fl[5]);
        ah[kb2][3] = pack_bf16(fh[6], fh[7]);  al[kb2][3] = pack_bf16(fl[6], fl[7]);
    }

    float m1[2] = {CUDART_INF_F, CUDART_INF_F};
    float m2[2] = {CUDART_INF_F, CUDART_INF_F};
    int   i1[2] = {0, 0};
    const float t1a = t1s[r0], t1b = t1s[r0 + 8];

    for (int chunk = 0; chunk < NCHUNKS; chunk++) {
        __syncthreads();
        // stage 16 tiles of packed b-fragments (32 KB, coalesced)
        {
            const uint4* src = g_wpk + chunk * (TPC * 4 * 32);
            #pragma unroll 4
            for (int i = tid; i < TPC * 4 * 32; i += BLOCK) wpk[i] = src[i];
        }
        __syncthreads();

        #pragma unroll 1
        for (int tl = 0; tl < TPC; tl++) {
            const int ct = chunk * TPC + tl;
            float ca0=0.f,ca1=0.f,ca2=0.f,ca3=0.f;   // xl * wh
            float cb0=0.f,cb1=0.f,cb2=0.f,cb3=0.f;   // xh * wl
            float cc0=0.f,cc1=0.f,cc2=0.f,cc3=0.f;   // xh * wh
            #pragma unroll
            for (int kb2 = 0; kb2 < 4; kb2++) {
                uint4 b = wpk[(tl * 4 + kb2) * 32 + lane];
                mma_bf16(ca0,ca1,ca2,ca3, al[kb2][0],al[kb2][1],al[kb2][2],al[kb2][3], b.x, b.y);
                mma_bf16(cb0,cb1,cb2,cb3, ah[kb2][0],ah[kb2][1],ah[kb2][2],ah[kb2][3], b.z, b.w);
                mma_bf16(cc0,cc1,cc2,cc3, ah[kb2][0],ah[kb2][1],ah[kb2][2],ah[kb2][3], b.x, b.y);
            }
            float d0 = __fadd_rn(__fadd_rn(ca0, cb0), cc0);
            float d1 = __fadd_rn(__fadd_rn(ca1, cb1), cc1);
            float d2 = __fadd_rn(__fadd_rn(ca2, cb2), cc2);
            float d3 = __fadd_rn(__fadd_rn(ca3, cb3), cc3);

            const int cA = ct * 8 + 2 * q;
            float t2a = t2s[cA], t2b = t2s[cA + 1];
            float dd;
            dd = __fsub_rn(__fadd_rn(t1a, t2a), __fmul_rn(2.0f, d0));
            if (dd < m1[0]) { m2[0] = m1[0]; m1[0] = dd; i1[0] = cA; } else m2[0] = fminf(m2[0], dd);
            dd = __fsub_rn(__fadd_rn(t1a, t2b), __fmul_rn(2.0f, d1));
            if (dd < m1[0]) { m2[0] = m1[0]; m1[0] = dd; i1[0] = cA + 1; } else m2[0] = fminf(m2[0], dd);
            dd = __fsub_rn(__fadd_rn(t1b, t2a), __fmul_rn(2.0f, d2));
            if (dd < m1[1]) { m2[1] = m1[1]; m1[1] = dd; i1[1] = cA; } else m2[1] = fminf(m2[1], dd);
            dd = __fsub_rn(__fadd_rn(t1b, t2b), __fmul_rn(2.0f, d3));
            if (dd < m1[1]) { m2[1] = m1[1]; m1[1] = dd; i1[1] = cA + 1; } else m2[1] = fminf(m2[1], dd);
        }
    }

    // merge across the 4 q-lanes (xor 1,2), first-index ties; ties force fallback
    #pragma unroll
    for (int r = 0; r < 2; r++) {
        float a1 = m1[r]; int ai = i1[r]; float a2 = m2[r];
        #pragma unroll
        for (int off = 1; off <= 2; off <<= 1) {
            float o1 = __shfl_xor_sync(0xffffffffu, a1, off);
            int   oi = __shfl_xor_sync(0xffffffffu, ai, off);
            float o2 = __shfl_xor_sync(0xffffffffu, a2, off);
            float hi = fmaxf(a1, o1);
            if (o1 < a1 || (o1 == a1 && oi < ai)) { a1 = o1; ai = oi; }
            a2 = fminf(fminf(a2, o2), hi);
        }
        if (q == 0) {
            int grow = (int)rowbase + warp * 16 + g + r * 8;
            g_idx[grow] = ai;
            // certificate: gap > 4*ulp(result) + 1.2e-5 (bf16-split dist error + grid)
            unsigned b = __float_as_uint(fmaxf(fabsf(a1), 1.0f));
            int e = (int)((b >> 23) & 0xffu);
            float ulp = __uint_as_float((unsigned)(e - 23) << 23);
            float thr = __fmaf_rn(4.0f, ulp, 1.2e-5f);
            if (!(a2 - a1 > thr)) {
                int p = atomicAdd(&g_nfall, 1);
                g_fall[p] = grow;
            }
        }
    }
}

// ---- phase B: exact rescan, smem-chunked, bit-exact reference arithmetic ----
__global__ __launch_bounds__(256) void vq_exact(
    const float* __restrict__ inp, const float* __restrict__ wt)
{
    __shared__ float wch[128 * 66];
    const int tid = threadIdx.x;
    const int lane = tid & 31;
    const int warp = tid >> 5;
    const int n = *((volatile int*)&g_nfall);
    const int per_pass = gridDim.x * 8;
    const int nbatch = (n + per_pass - 1) / per_pass;

    for (int b = 0; b < nbatch; b++) {
        int ri = (b * gridDim.x + blockIdx.x) * 8 + warp;
        bool valid = ri < n;
        int row = valid ? g_fall[ri] : 0;

        float x[DDIM];
        {
            const float4* xr = reinterpret_cast<const float4*>(inp + (size_t)row * DDIM);
            #pragma unroll
            for (int k4 = 0; k4 < 16; k4++) {
                float4 v = xr[k4];
                x[4*k4]=v.x; x[4*k4+1]=v.y; x[4*k4+2]=v.z; x[4*k4+3]=v.w;
            }
        }
        float t1 = 0.0f;
        #pragma unroll
        for (int k = 0; k < DDIM; k++)
            t1 = __fadd_rn(t1, __fmul_rn(x[k], x[k]));

        float best = CUDART_INF_F; int bi = 0;
        for (int ch = 0; ch < 8; ch++) {
            __syncthreads();
            for (int i = tid; i < 128 * DDIM; i += 256)
                wch[(i >> 6) * 66 + (i & 63)] = wt[ch * 128 * DDIM + i];
            __syncthreads();
            if (valid) {
                #pragma unroll
                for (int j = 0; j < 4; j++) {
                    int cl = lane + 32 * j;
                    const float* wr = wch + cl * 66;
                    float dacc = 0.0f;
                    #pragma unroll
                    for (int k = 0; k < DDIM; k++)
                        dacc = __fmaf_rn(x[k], wr[k], dacc);
                    int c = ch * 128 + cl;
                    float u = __fadd_rn(t1, g_t2[c]);
                    float dist = __fsub_rn(u, __fmul_rn(2.0f, dacc));
                    if (dist < best) { best = dist; bi = c; }
                }
            }
        }
        #pragma unroll
        for (int off = 1; off < 32; off <<= 1) {
            float ob = __shfl_xor_sync(0xffffffffu, best, off);
            int   oi = __shfl_xor_sync(0xffffffffu, bi, off);
            if (ob < best || (ob == best && oi < bi)) { best = ob; bi = oi; }
        }
        if (valid && lane == 0) g_idx[row] = bi;
    }
}

// ---- phase C: scatter ones + quantized + loss ----
__global__ __launch_bounds__(BLOCK) void vq_out(
    const float* __restrict__ inp, const float* __restrict__ wt,
    float* out_q, float* out_enc, float* out_loss)
{
    __shared__ int   idx_sh[RPB];
    __shared__ float red[BLOCK];
    const int tid = threadIdx.x;
    const size_t rowbase = (size_t)blockIdx.x * RPB;

    if (tid < RPB) idx_sh[tid] = g_idx[rowbase + tid];
    __syncthreads();

    if (out_enc && tid < RPB)
        out_enc[(rowbase + tid) * (size_t)ECODES + (size_t)idx_sh[tid]] = 1.0f;

    float part = 0.0f;
    for (int i = tid; i < RPB * DDIM; i += BLOCK) {
        int r = i >> 6, k = i & 63;
        float qv = wt[(size_t)idx_sh[r] * DDIM + k];
        float xv = inp[(rowbase + r) * DDIM + k];
        float dqx = __fsub_rn(qv, xv);
        part = __fadd_rn(part, __fmul_rn(dqx, dqx));
        if (out_q)
            out_q[rowbase * DDIM + i] = __fadd_rn(xv, dqx);
    }
    red[tid] = part;
    __syncthreads();
    for (int s = BLOCK / 2; s > 0; s >>= 1) {
        if (tid < s) red[tid] += red[tid + s];
        __syncthreads();
    }
    if (tid == 0) {
        atomicAdd(&g_loss_acc, red[0]);
        __threadfence();
        unsigned int done = atomicAdd(&g_ctr, 1u);
        if (done == GRID_A - 1) {
            float m = *((volatile float*)&g_loss_acc) / 8388608.0f;
            if (out_loss) out_loss[0] = __fadd_rn(m, __fmul_rn(0.25f, m));
            g_loss_acc = 0.0f;
            __threadfence();
            g_ctr = 0u;
        }
    }
}

extern "C" void kernel_launch(void* const* d_in, const int* in_sizes, int n_in,
                              void* d_out, int out_size)
{
    const float* inp = nullptr;
    const float* wt  = nullptr;
    for (int i = 0; i < n_in; i++) {
        if (in_sizes[i] == 8388608) inp = (const float*)d_in[i];
        else if (in_sizes[i] == 65536) wt = (const float*)d_in[i];
    }
    if (!inp || !wt) return;

    float* out = (float*)d_out;
    const long long Q = 8388608LL, ENC = 134217728LL;
    long long os = (long long)out_size;

    float* oL = nullptr; float* oQ = nullptr; float* oE = nullptr;
    if (os == 1 + Q + ENC)      { oL = out; oQ = out + 1; oE = out + 1 + Q; }
    else if (os == Q + ENC)     { oQ = out; oE = out + Q; }
    else if (os == ENC)         { oE = out; }
    else if (os == Q)           { oQ = out; }
    else if (os == 1)           { oL = out; }
    else {
        oL = out;
        if (os >= 1 + Q) oQ = out + 1;
        if (os >= 1 + Q + ENC) oE = out + 1 + Q;
    }

    cudaFuncSetAttribute(vq_filter,
                         cudaFuncAttributeMaxDynamicSharedMemorySize, SMEMF);

    vq_prep<<<4, 256>>>(wt);
    vq_filter<<<GRID_A, BLOCK, SMEMF>>>(inp, oE);
    vq_exact<<<148, 256>>>(inp, wt);
    vq_out<<<GRID_A, BLOCK>>>(inp, wt, oQ, oE, oL);
}